// round 1
// baseline (speedup 1.0000x reference)
#include <cuda_runtime.h>
#include <math.h>

#define NN 50000
#define EE 500000
#define GG 100
#define NPG 500
#define NPROT 400
#define HD 128
#define PNF 35
#define LNF 11
#define NL 4
#define BN_EPS 1e-5f

// ---------------- scratch (device globals; no allocation allowed) ----------------
__device__ float g_h[NN * HD];
__device__ float g_hA[NN * HD];
__device__ float g_hB[NN * HD];
__device__ float g_agg[NN * HD];
__device__ float g_u1[NN * HD];
__device__ float g_pos[NN * 3];
__device__ float g_posacc[NN * 3];
__device__ float g_deg[NN];
__device__ float g_stats[2 * HD];

__device__ __forceinline__ float siluf(float x) { return x / (1.f + __expf(-x)); }

// ---------------- init: zero scratch, copy pos ----------------
__global__ void k_init(const float* __restrict__ pos) {
    int stride = gridDim.x * blockDim.x;
    for (int i = blockIdx.x * blockDim.x + threadIdx.x; i < NN * HD; i += stride) {
        g_agg[i] = 0.f;
        if (i < NN * 3) { g_pos[i] = pos[i]; g_posacc[i] = 0.f; }
        if (i < NN) g_deg[i] = 0.f;
        if (i < 2 * HD) g_stats[i] = 0.f;
    }
}

__global__ void k_deg(const int* __restrict__ ei) {
    int i = blockIdx.x * blockDim.x + threadIdx.x;
    if (i < EE) atomicAdd(&g_deg[ei[i]], 1.f);
}

// ---------------- input projection (protein/ligand select) ----------------
__global__ void k_proj(const float* __restrict__ x,
                       const float* __restrict__ Wp, const float* __restrict__ bp,
                       const float* __restrict__ Wl, const float* __restrict__ bl) {
    int f = threadIdx.x;  // 128 threads
    for (int n = blockIdx.x; n < NN; n += gridDim.x) {
        const float* xr = x + n * PNF;
        float acc;
        if ((n % NPG) < NPROT) {
            acc = bp[f];
#pragma unroll
            for (int k = 0; k < PNF; k++) acc += xr[k] * Wp[k * HD + f];
        } else {
            acc = bl[f];
#pragma unroll
            for (int k = 0; k < LNF; k++) acc += xr[k] * Wl[k * HD + f];
        }
        g_h[n * HD + f] = acc;
    }
}

// ---------------- batchnorm (training-mode batch stats) ----------------
__global__ void k_stats() {
    int f = threadIdx.x;
    float s = 0.f, s2 = 0.f;
    for (int n = blockIdx.x; n < NN; n += gridDim.x) {
        float v = g_h[n * HD + f];
        s += v; s2 += v * v;
    }
    atomicAdd(&g_stats[f], s);
    atomicAdd(&g_stats[HD + f], s2);
}

__global__ void k_bn(const float* __restrict__ gam, const float* __restrict__ bet) {
    int stride = gridDim.x * blockDim.x;
    for (int i = blockIdx.x * blockDim.x + threadIdx.x; i < NN * HD; i += stride) {
        int f = i & (HD - 1);
        float mu = g_stats[f] * (1.f / NN);
        float var = g_stats[HD + f] * (1.f / NN) - mu * mu;
        g_h[i] = (g_h[i] - mu) * rsqrtf(var + BN_EPS) * gam[f] + bet[f];
    }
}

// ---------------- generic node GEMM: Y = [silu?](X @ W [+ bias] [+ R]) ----------------
// X:[N,128], W:[128,128]. 128-row tiles, 256 threads, 8x8 micro-tile.
#define XPAD 129
template <bool SILU_, bool BIAS_, bool RESID_>
__global__ void k_gemm(const float* __restrict__ X, const float* __restrict__ W,
                       const float* __restrict__ bias, const float* __restrict__ R,
                       float* __restrict__ Y) {
    extern __shared__ float sm[];
    float* sW = sm;                 // 128*128
    float* sX = sm + HD * HD;       // 128*XPAD
    int tid = threadIdx.x;
    int base = blockIdx.x * 128;
    const float4* W4 = (const float4*)W;
    float4* sW4 = (float4*)sW;
#pragma unroll
    for (int i = 0; i < 16; i++) sW4[tid + 256 * i] = W4[tid + 256 * i];
    for (int i = tid; i < 128 * HD; i += 256) {
        int r = i >> 7, c = i & 127;
        int gr = base + r;
        sX[r * XPAD + c] = (gr < NN) ? X[gr * HD + c] : 0.f;
    }
    __syncthreads();
    int ti = tid >> 4, tj = tid & 15;
    int r0 = ti * 8, c0 = tj * 8;
    float acc[8][8];
#pragma unroll
    for (int r = 0; r < 8; r++)
#pragma unroll
        for (int c = 0; c < 8; c++) acc[r][c] = BIAS_ ? bias[c0 + c] : 0.f;
#pragma unroll 8
    for (int k = 0; k < HD; k++) {
        float a[8];
#pragma unroll
        for (int r = 0; r < 8; r++) a[r] = sX[(r0 + r) * XPAD + k];
        float4 w0 = *(const float4*)&sW[k * HD + c0];
        float4 w1 = *(const float4*)&sW[k * HD + c0 + 4];
#pragma unroll
        for (int r = 0; r < 8; r++) {
            acc[r][0] += a[r] * w0.x; acc[r][1] += a[r] * w0.y;
            acc[r][2] += a[r] * w0.z; acc[r][3] += a[r] * w0.w;
            acc[r][4] += a[r] * w1.x; acc[r][5] += a[r] * w1.y;
            acc[r][6] += a[r] * w1.z; acc[r][7] += a[r] * w1.w;
        }
    }
#pragma unroll
    for (int r = 0; r < 8; r++) {
        int gr = base + r0 + r;
        if (gr < NN) {
#pragma unroll
            for (int c = 0; c < 8; c++) {
                float v = acc[r][c];
                if (SILU_) v = siluf(v);
                if (RESID_) v += R[gr * HD + c0 + c];
                Y[gr * HD + c0 + c] = v;
            }
        }
    }
}

// ---------------- dual-input node GEMM: Y = silu(X1@W1 + X2@W2 + bias) ----------------
// 64-row tiles, 256 threads, 4x8 micro-tile.
__global__ void k_dual(const float* __restrict__ X1, const float* __restrict__ W1,
                       const float* __restrict__ X2, const float* __restrict__ W2,
                       const float* __restrict__ bias, float* __restrict__ Y) {
    extern __shared__ float sm[];
    float* sW1 = sm;
    float* sW2 = sm + 16384;
    float* sX1 = sm + 32768;            // 64*XPAD
    float* sX2 = sX1 + 64 * XPAD;
    int tid = threadIdx.x;
    int base = blockIdx.x * 64;
    const float4* w14 = (const float4*)W1;
    const float4* w24 = (const float4*)W2;
#pragma unroll
    for (int i = 0; i < 16; i++) {
        ((float4*)sW1)[tid + 256 * i] = w14[tid + 256 * i];
        ((float4*)sW2)[tid + 256 * i] = w24[tid + 256 * i];
    }
    for (int i = tid; i < 64 * HD; i += 256) {
        int r = i >> 7, c = i & 127;
        int gr = base + r;
        float v1 = 0.f, v2 = 0.f;
        if (gr < NN) { v1 = X1[gr * HD + c]; v2 = X2[gr * HD + c]; }
        sX1[r * XPAD + c] = v1;
        sX2[r * XPAD + c] = v2;
    }
    __syncthreads();
    int ti = tid >> 4, tj = tid & 15;
    int r0 = ti * 4, c0 = tj * 8;
    float acc[4][8];
#pragma unroll
    for (int r = 0; r < 4; r++)
#pragma unroll
        for (int c = 0; c < 8; c++) acc[r][c] = bias[c0 + c];
#pragma unroll 8
    for (int k = 0; k < HD; k++) {
        float a1[4], a2[4];
#pragma unroll
        for (int r = 0; r < 4; r++) { a1[r] = sX1[(r0 + r) * XPAD + k]; a2[r] = sX2[(r0 + r) * XPAD + k]; }
        float4 u0 = *(const float4*)&sW1[k * HD + c0];
        float4 u1 = *(const float4*)&sW1[k * HD + c0 + 4];
        float4 v0 = *(const float4*)&sW2[k * HD + c0];
        float4 v1 = *(const float4*)&sW2[k * HD + c0 + 4];
#pragma unroll
        for (int r = 0; r < 4; r++) {
            acc[r][0] += a1[r] * u0.x + a2[r] * v0.x;
            acc[r][1] += a1[r] * u0.y + a2[r] * v0.y;
            acc[r][2] += a1[r] * u0.z + a2[r] * v0.z;
            acc[r][3] += a1[r] * u0.w + a2[r] * v0.w;
            acc[r][4] += a1[r] * u1.x + a2[r] * v1.x;
            acc[r][5] += a1[r] * u1.y + a2[r] * v1.y;
            acc[r][6] += a1[r] * u1.z + a2[r] * v1.z;
            acc[r][7] += a1[r] * u1.w + a2[r] * v1.w;
        }
    }
#pragma unroll
    for (int r = 0; r < 4; r++) {
        int gr = base + r0 + r;
        if (gr < NN) {
#pragma unroll
            for (int c = 0; c < 8; c++) Y[gr * HD + c0 + c] = siluf(acc[r][c]);
        }
    }
}

// ---------------- fused edge kernel ----------------
// Per 64-edge tile:
//   t = silu(hA[row] + hB[col] + d2*wd + ea@W1e)       (hA already holds X@W1a + e_b1)
//   m = silu(t @ e_w2 + e_b2)    -> atomic agg[row] += m
//   w = sum_c silu(m @ c_w1 + c_b1)[c] * c_w2[c]       -> atomic posacc[row] += rel*w
__global__ void k_edge(const int* __restrict__ ei, const float* __restrict__ ea,
                       const float* __restrict__ w1tail,   // e_w1[l] rows 256..260 (5*128)
                       const float* __restrict__ eW2, const float* __restrict__ eB2,
                       const float* __restrict__ cW1, const float* __restrict__ cB1,
                       const float* __restrict__ cW2) {
    extern __shared__ float sm[];
    float* sW2 = sm;                      // 16384
    float* sC1 = sW2 + 16384;             // 16384
    float* sT  = sC1 + 16384;             // 64*XPAD = 8256
    float* sM  = sT + 64 * XPAD;          // 8256
    float* sWd = sM + 64 * XPAD;          // 128
    float* sW1e = sWd + 128;              // 512
    float* sB2 = sW1e + 512;              // 128
    float* sCb = sB2 + 128;               // 128
    float* sC2 = sCb + 128;               // 128
    float* sD2 = sC2 + 128;               // 64
    float* sRel = sD2 + 64;               // 192
    float* sWs = sRel + 192;              // 64
    float* sEA = sWs + 64;                // 256
    int* sRow = (int*)(sEA + 256);        // 64
    int* sCol = sRow + 64;                // 64

    int tid = threadIdx.x;
    int base = blockIdx.x * 64;
    int ne = EE - base; if (ne > 64) ne = 64;

    const float4* w24g = (const float4*)eW2;
    const float4* c14g = (const float4*)cW1;
#pragma unroll
    for (int i = 0; i < 16; i++) {
        ((float4*)sW2)[tid + 256 * i] = w24g[tid + 256 * i];
        ((float4*)sC1)[tid + 256 * i] = c14g[tid + 256 * i];
    }
    for (int i = tid; i < 5 * HD; i += 256) {
        float v = w1tail[i];
        if (i < HD) sWd[i] = v; else sW1e[i - HD] = v;
    }
    if (tid < HD) { sB2[tid] = eB2[tid]; sCb[tid] = cB1[tid]; sC2[tid] = cW2[tid]; }
    if (tid < 64) {
        if (tid < ne) {
            int e = base + tid;
            int r = ei[e], c = ei[EE + e];
            sRow[tid] = r; sCol[tid] = c;
            float rx = g_pos[r * 3 + 0] - g_pos[c * 3 + 0];
            float ry = g_pos[r * 3 + 1] - g_pos[c * 3 + 1];
            float rz = g_pos[r * 3 + 2] - g_pos[c * 3 + 2];
            sRel[tid * 3 + 0] = rx; sRel[tid * 3 + 1] = ry; sRel[tid * 3 + 2] = rz;
            sD2[tid] = rx * rx + ry * ry + rz * rz;
#pragma unroll
            for (int k = 0; k < 4; k++) sEA[tid * 4 + k] = ea[e * 4 + k];
        } else {
            sRow[tid] = 0; sCol[tid] = 0; sD2[tid] = 0.f;
            sRel[tid * 3] = 0.f; sRel[tid * 3 + 1] = 0.f; sRel[tid * 3 + 2] = 0.f;
#pragma unroll
            for (int k = 0; k < 4; k++) sEA[tid * 4 + k] = 0.f;
        }
    }
    __syncthreads();

    // t-phase: one warp per edge row (coalesced 512B gathers)
    const float4* hA4 = (const float4*)g_hA;
    const float4* hB4 = (const float4*)g_hB;
#pragma unroll
    for (int it = 0; it < 8; it++) {
        int i = tid + it * 256;
        int e = i >> 5, jg = i & 31;
        float vx = 0.f, vy = 0.f, vz = 0.f, vw = 0.f;
        if (e < ne) {
            float4 a = hA4[sRow[e] * 32 + jg];
            float4 b = hB4[sCol[e] * 32 + jg];
            float d2 = sD2[e];
            float4 wd = ((const float4*)sWd)[jg];
            vx = a.x + b.x + d2 * wd.x;
            vy = a.y + b.y + d2 * wd.y;
            vz = a.z + b.z + d2 * wd.z;
            vw = a.w + b.w + d2 * wd.w;
#pragma unroll
            for (int k = 0; k < 4; k++) {
                float ek = sEA[e * 4 + k];
                float4 we = ((const float4*)sW1e)[k * 32 + jg];
                vx += ek * we.x; vy += ek * we.y; vz += ek * we.z; vw += ek * we.w;
            }
            vx = siluf(vx); vy = siluf(vy); vz = siluf(vz); vw = siluf(vw);
        }
        int off = e * XPAD + jg * 4;
        sT[off] = vx; sT[off + 1] = vy; sT[off + 2] = vz; sT[off + 3] = vw;
    }
    __syncthreads();

    int ti = tid >> 4, tj = tid & 15;
    int e0 = ti * 4, c0 = tj * 8;

    // GEMM1: m = silu(t @ e_w2 + b2)
    float acc[4][8];
#pragma unroll
    for (int r = 0; r < 4; r++)
#pragma unroll
        for (int c = 0; c < 8; c++) acc[r][c] = sB2[c0 + c];
#pragma unroll 8
    for (int k = 0; k < HD; k++) {
        float a[4];
#pragma unroll
        for (int r = 0; r < 4; r++) a[r] = sT[(e0 + r) * XPAD + k];
        float4 w0 = *(const float4*)&sW2[k * HD + c0];
        float4 w1 = *(const float4*)&sW2[k * HD + c0 + 4];
#pragma unroll
        for (int r = 0; r < 4; r++) {
            acc[r][0] += a[r] * w0.x; acc[r][1] += a[r] * w0.y;
            acc[r][2] += a[r] * w0.z; acc[r][3] += a[r] * w0.w;
            acc[r][4] += a[r] * w1.x; acc[r][5] += a[r] * w1.y;
            acc[r][6] += a[r] * w1.z; acc[r][7] += a[r] * w1.w;
        }
    }
#pragma unroll
    for (int r = 0; r < 4; r++) {
        int e = e0 + r;
        bool valid = e < ne;
        int rb = valid ? sRow[e] * HD : 0;
#pragma unroll
        for (int c = 0; c < 8; c++) {
            float m = siluf(acc[r][c]);
            sM[e * XPAD + c0 + c] = m;
            if (valid) atomicAdd(&g_agg[rb + c0 + c], m);
        }
    }
    __syncthreads();

    // GEMM2: cm = silu(m @ c_w1 + cb1);  w = cm . c_w2
    float acc2[4][8];
#pragma unroll
    for (int r = 0; r < 4; r++)
#pragma unroll
        for (int c = 0; c < 8; c++) acc2[r][c] = sCb[c0 + c];
#pragma unroll 8
    for (int k = 0; k < HD; k++) {
        float a[4];
#pragma unroll
        for (int r = 0; r < 4; r++) a[r] = sM[(e0 + r) * XPAD + k];
        float4 w0 = *(const float4*)&sC1[k * HD + c0];
        float4 w1 = *(const float4*)&sC1[k * HD + c0 + 4];
#pragma unroll
        for (int r = 0; r < 4; r++) {
            acc2[r][0] += a[r] * w0.x; acc2[r][1] += a[r] * w0.y;
            acc2[r][2] += a[r] * w0.z; acc2[r][3] += a[r] * w0.w;
            acc2[r][4] += a[r] * w1.x; acc2[r][5] += a[r] * w1.y;
            acc2[r][6] += a[r] * w1.z; acc2[r][7] += a[r] * w1.w;
        }
    }
    float wp[4];
#pragma unroll
    for (int r = 0; r < 4; r++) {
        float s = 0.f;
#pragma unroll
        for (int c = 0; c < 8; c++) s += siluf(acc2[r][c]) * sC2[c0 + c];
        wp[r] = s;
    }
#pragma unroll
    for (int o = 1; o < 16; o <<= 1) {
#pragma unroll
        for (int r = 0; r < 4; r++) wp[r] += __shfl_xor_sync(0xffffffffu, wp[r], o);
    }
    if (tj == 0) {
#pragma unroll
        for (int r = 0; r < 4; r++) sWs[e0 + r] = wp[r];
    }
    __syncthreads();
    if (tid < ne) {
        float w = sWs[tid];
        int rb = sRow[tid] * 3;
        atomicAdd(&g_posacc[rb + 0], sRel[tid * 3 + 0] * w);
        atomicAdd(&g_posacc[rb + 1], sRel[tid * 3 + 1] * w);
        atomicAdd(&g_posacc[rb + 2], sRel[tid * 3 + 2] * w);
    }
}

// ---------------- pos update + per-layer scratch reset ----------------
__global__ void k_posupd() {
    int stride = gridDim.x * blockDim.x;
    for (int i = blockIdx.x * blockDim.x + threadIdx.x; i < NN * HD; i += stride) {
        g_agg[i] = 0.f;
        if (i < NN * 3) {
            g_pos[i] += g_posacc[i] / fmaxf(g_deg[i / 3], 1.f);
            g_posacc[i] = 0.f;
        }
    }
}

// ---------------- pooling + MLP head ----------------
__global__ void k_head(const float* __restrict__ h1w, const float* __restrict__ h1b,
                       const float* __restrict__ h2w, const float* __restrict__ h2b,
                       const float* __restrict__ h3w, const float* __restrict__ h3b,
                       float* __restrict__ out) {
    __shared__ float sg[2 * HD];
    __shared__ float sz1[128];
    __shared__ float sz2[64];
    int g = blockIdx.x;
    int f = threadIdx.x;  // 128 threads
    float acc = 0.f;
    int nb = g * NPG;
    for (int n = 0; n < NPG; n++) acc += g_h[(nb + n) * HD + f];
    sg[f] = acc;
    sg[HD + f] = acc * (1.f / NPG);
    __syncthreads();
    float z = h1b[f];
    for (int k = 0; k < 2 * HD; k++) z += sg[k] * h1w[k * 128 + f];
    sz1[f] = fmaxf(z, 0.f);
    __syncthreads();
    if (f < 64) {
        float z2 = h2b[f];
        for (int k = 0; k < 128; k++) z2 += sz1[k] * h2w[k * 64 + f];
        sz2[f] = fmaxf(z2, 0.f);
    }
    __syncthreads();
    if (f == 0) {
        float o = h3b[0];
        for (int k = 0; k < 64; k++) o += sz2[k] * h3w[k];
        out[g] = o;
    }
}

// ---------------- host orchestration ----------------
extern "C" void kernel_launch(void* const* d_in, const int* in_sizes, int n_in,
                              void* d_out, int out_size) {
    (void)in_sizes; (void)n_in; (void)out_size;
    const float* x    = (const float*)d_in[0];
    const float* pos  = (const float*)d_in[1];
    const int*   ei   = (const int*)d_in[2];
    const float* ea   = (const float*)d_in[3];
    const float* Wp   = (const float*)d_in[6];
    const float* bp   = (const float*)d_in[7];
    const float* Wl   = (const float*)d_in[8];
    const float* bl   = (const float*)d_in[9];
    const float* bng  = (const float*)d_in[10];
    const float* bnb  = (const float*)d_in[11];
    const float* e_w1 = (const float*)d_in[12];
    const float* e_b1 = (const float*)d_in[13];
    const float* e_w2 = (const float*)d_in[14];
    const float* e_b2 = (const float*)d_in[15];
    const float* c_w1 = (const float*)d_in[16];
    const float* c_b1 = (const float*)d_in[17];
    const float* c_w2 = (const float*)d_in[18];
    const float* n_w1 = (const float*)d_in[19];
    const float* n_b1 = (const float*)d_in[20];
    const float* n_w2 = (const float*)d_in[21];
    const float* n_b2 = (const float*)d_in[22];
    const float* h1w  = (const float*)d_in[23];
    const float* h1b  = (const float*)d_in[24];
    const float* h2w  = (const float*)d_in[25];
    const float* h2b  = (const float*)d_in[26];
    const float* h3w  = (const float*)d_in[27];
    const float* h3b  = (const float*)d_in[28];
    float* out = (float*)d_out;

    float *p_h, *p_hA, *p_hB, *p_agg, *p_u1;
    cudaGetSymbolAddress((void**)&p_h,   g_h);
    cudaGetSymbolAddress((void**)&p_hA,  g_hA);
    cudaGetSymbolAddress((void**)&p_hB,  g_hB);
    cudaGetSymbolAddress((void**)&p_agg, g_agg);
    cudaGetSymbolAddress((void**)&p_u1,  g_u1);

    const int smem_gemm = (128 * 128 + 128 * XPAD) * 4;
    const int smem_dual = (2 * 128 * 128 + 2 * 64 * XPAD) * 4;
    const int smem_edge = (16384 * 2 + 2 * 64 * XPAD + 128 + 512 + 128 * 3 + 64 + 192 + 64 + 256 + 128) * 4;

    cudaFuncSetAttribute(k_gemm<false, true, false>,  cudaFuncAttributeMaxDynamicSharedMemorySize, smem_gemm);
    cudaFuncSetAttribute(k_gemm<false, false, false>, cudaFuncAttributeMaxDynamicSharedMemorySize, smem_gemm);
    cudaFuncSetAttribute(k_gemm<false, true, true>,   cudaFuncAttributeMaxDynamicSharedMemorySize, smem_gemm);
    cudaFuncSetAttribute(k_dual, cudaFuncAttributeMaxDynamicSharedMemorySize, smem_dual);
    cudaFuncSetAttribute(k_edge, cudaFuncAttributeMaxDynamicSharedMemorySize, smem_edge);

    k_init<<<2048, 256>>>(pos);
    k_proj<<<2048, 128>>>(x, Wp, bp, Wl, bl);
    k_stats<<<512, 128>>>();
    k_bn<<<2048, 256>>>(bng, bnb);
    k_deg<<<(EE + 255) / 256, 256>>>(ei);

    for (int l = 0; l < NL; l++) {
        const float* w1l = e_w1 + (size_t)l * 261 * HD;
        // hA = h @ W1a + e_b1[l];  hB = h @ W1b
        k_gemm<false, true, false><<<391, 256, smem_gemm>>>(p_h, w1l, e_b1 + l * HD, nullptr, p_hA);
        k_gemm<false, false, false><<<391, 256, smem_gemm>>>(p_h, w1l + 128 * HD, nullptr, nullptr, p_hB);
        // fused edge MLP + scatters
        k_edge<<<(EE + 63) / 64, 256, smem_edge>>>(
            ei, ea, w1l + 256 * HD,
            e_w2 + (size_t)l * HD * HD, e_b2 + l * HD,
            c_w1 + (size_t)l * HD * HD, c_b1 + l * HD, c_w2 + l * HD);
        // u1 = silu(h @ nW1a + agg @ nW1b + n_b1[l])
        k_dual<<<782, 256, smem_dual>>>(p_h, n_w1 + (size_t)l * 2 * HD * HD,
                                        p_agg, n_w1 + (size_t)l * 2 * HD * HD + 128 * HD,
                                        n_b1 + l * HD, p_u1);
        // pos += posacc/deg; zero agg/posacc for next layer
        k_posupd<<<2048, 256>>>();
        // h = h + u1 @ n_w2[l] + n_b2[l]
        k_gemm<false, true, true><<<391, 256, smem_gemm>>>(p_u1, n_w2 + (size_t)l * HD * HD,
                                                           n_b2 + l * HD, p_h, p_h);
    }

    k_head<<<GG, 128>>>(h1w, h1b, h2w, h2b, h3w, h3b, out);
}

// round 4
// speedup vs baseline: 1.6103x; 1.6103x over previous
#include <cuda_runtime.h>
#include <cuda_bf16.h>
#include <math.h>
#include <stdint.h>

#define NN 50000
#define EE 500000
#define GG 100
#define NPG 500
#define NPROT 400
#define HD 128
#define PNF 35
#define LNF 11
#define NL 4
#define BN_EPS 1e-5f

#define XPAD 129
// edge tensor-core kernel tiling
#define WS 68           // word stride for packed-bf16 tiles (128 halves + pad) -> banks 4*gid+tg
#define ET 128          // edges per tile
#define NT ((EE + ET - 1) / ET)

// ---------------- scratch (device globals; no allocation allowed) ----------------
__device__ float g_h[NN * HD];
__device__ float g_hA[NN * HD];
__device__ float g_hB[NN * HD];
__device__ float g_agg[NN * HD];
__device__ float g_u1[NN * HD];
__device__ float g_pos[NN * 3];
__device__ float g_posacc[NN * 3];
__device__ float g_deg[NN];
__device__ float g_stats[2 * HD];

__device__ __forceinline__ float siluf(float x) { return x / (1.f + __expf(-x)); }

__device__ __forceinline__ uint32_t pack2bf(float lo, float hi) {
    __nv_bfloat162 t = __floats2bfloat162_rn(lo, hi);  // .x = lo half, .y = hi half
    return *(uint32_t*)&t;
}

// split v = hi + lo, both exactly representable in bf16
__device__ __forceinline__ void bsplit(float v, float& h, float& l) {
    h = __bfloat162float(__float2bfloat16_rn(v));
    l = v - h;
}

__device__ __forceinline__ void mma_bf16(float c[4], const uint32_t a[4],
                                         uint32_t b0, uint32_t b1) {
    asm volatile(
        "mma.sync.aligned.m16n8k16.row.col.f32.bf16.bf16.f32 "
        "{%0,%1,%2,%3},{%4,%5,%6,%7},{%8,%9},{%0,%1,%2,%3};"
        : "+f"(c[0]), "+f"(c[1]), "+f"(c[2]), "+f"(c[3])
        : "r"(a[0]), "r"(a[1]), "r"(a[2]), "r"(a[3]), "r"(b0), "r"(b1));
}

__device__ __forceinline__ void red2(float* p, float x, float y) {
    asm volatile("red.global.add.v2.f32 [%0], {%1, %2};" :: "l"(p), "f"(x), "f"(y) : "memory");
}

// ---------------- init: zero scratch, copy pos ----------------
__global__ void k_init(const float* __restrict__ pos) {
    int stride = gridDim.x * blockDim.x;
    for (int i = blockIdx.x * blockDim.x + threadIdx.x; i < NN * HD; i += stride) {
        g_agg[i] = 0.f;
        if (i < NN * 3) { g_pos[i] = pos[i]; g_posacc[i] = 0.f; }
        if (i < NN) g_deg[i] = 0.f;
        if (i < 2 * HD) g_stats[i] = 0.f;
    }
}

__global__ void k_deg(const int* __restrict__ ei) {
    int i = blockIdx.x * blockDim.x + threadIdx.x;
    if (i < EE) atomicAdd(&g_deg[ei[i]], 1.f);
}

// ---------------- input projection (protein/ligand select) ----------------
__global__ void k_proj(const float* __restrict__ x,
                       const float* __restrict__ Wp, const float* __restrict__ bp,
                       const float* __restrict__ Wl, const float* __restrict__ bl) {
    int f = threadIdx.x;  // 128 threads
    for (int n = blockIdx.x; n < NN; n += gridDim.x) {
        const float* xr = x + n * PNF;
        float acc;
        if ((n % NPG) < NPROT) {
            acc = bp[f];
#pragma unroll
            for (int k = 0; k < PNF; k++) acc += xr[k] * Wp[k * HD + f];
        } else {
            acc = bl[f];
#pragma unroll
            for (int k = 0; k < LNF; k++) acc += xr[k] * Wl[k * HD + f];
        }
        g_h[n * HD + f] = acc;
    }
}

// ---------------- batchnorm (training-mode batch stats) ----------------
__global__ void k_stats() {
    int f = threadIdx.x;
    float s = 0.f, s2 = 0.f;
    for (int n = blockIdx.x; n < NN; n += gridDim.x) {
        float v = g_h[n * HD + f];
        s += v; s2 += v * v;
    }
    atomicAdd(&g_stats[f], s);
    atomicAdd(&g_stats[HD + f], s2);
}

__global__ void k_bn(const float* __restrict__ gam, const float* __restrict__ bet) {
    int stride = gridDim.x * blockDim.x;
    for (int i = blockIdx.x * blockDim.x + threadIdx.x; i < NN * HD; i += stride) {
        int f = i & (HD - 1);
        float mu = g_stats[f] * (1.f / NN);
        float var = g_stats[HD + f] * (1.f / NN) - mu * mu;
        g_h[i] = (g_h[i] - mu) * rsqrtf(var + BN_EPS) * gam[f] + bet[f];
    }
}

// ---------------- generic node GEMM: Y = X @ W [+ bias] [+ R] ----------------
template <bool SILU_, bool BIAS_, bool RESID_>
__global__ void k_gemm(const float* __restrict__ X, const float* __restrict__ W,
                       const float* __restrict__ bias, const float* __restrict__ R,
                       float* __restrict__ Y) {
    extern __shared__ float sm[];
    float* sW = sm;                 // 128*128
    float* sX = sm + HD * HD;       // 128*XPAD
    int tid = threadIdx.x;
    int base = blockIdx.x * 128;
    const float4* W4 = (const float4*)W;
    float4* sW4 = (float4*)sW;
#pragma unroll
    for (int i = 0; i < 16; i++) sW4[tid + 256 * i] = W4[tid + 256 * i];
    for (int i = tid; i < 128 * HD; i += 256) {
        int r = i >> 7, c = i & 127;
        int gr = base + r;
        sX[r * XPAD + c] = (gr < NN) ? X[gr * HD + c] : 0.f;
    }
    __syncthreads();
    int ti = tid >> 4, tj = tid & 15;
    int r0 = ti * 8, c0 = tj * 8;
    float acc[8][8];
#pragma unroll
    for (int r = 0; r < 8; r++)
#pragma unroll
        for (int c = 0; c < 8; c++) acc[r][c] = BIAS_ ? bias[c0 + c] : 0.f;
#pragma unroll 8
    for (int k = 0; k < HD; k++) {
        float a[8];
#pragma unroll
        for (int r = 0; r < 8; r++) a[r] = sX[(r0 + r) * XPAD + k];
        float4 w0 = *(const float4*)&sW[k * HD + c0];
        float4 w1 = *(const float4*)&sW[k * HD + c0 + 4];
#pragma unroll
        for (int r = 0; r < 8; r++) {
            acc[r][0] += a[r] * w0.x; acc[r][1] += a[r] * w0.y;
            acc[r][2] += a[r] * w0.z; acc[r][3] += a[r] * w0.w;
            acc[r][4] += a[r] * w1.x; acc[r][5] += a[r] * w1.y;
            acc[r][6] += a[r] * w1.z; acc[r][7] += a[r] * w1.w;
        }
    }
#pragma unroll
    for (int r = 0; r < 8; r++) {
        int gr = base + r0 + r;
        if (gr < NN) {
#pragma unroll
            for (int c = 0; c < 8; c++) {
                float v = acc[r][c];
                if (SILU_) v = siluf(v);
                if (RESID_) v += R[gr * HD + c0 + c];
                Y[gr * HD + c0 + c] = v;
            }
        }
    }
}

// ---------------- dual-input node GEMM: Y = silu(X1@W1 + X2@W2 + bias) ----------------
__global__ void k_dual(const float* __restrict__ X1, const float* __restrict__ W1,
                       const float* __restrict__ X2, const float* __restrict__ W2,
                       const float* __restrict__ bias, float* __restrict__ Y) {
    extern __shared__ float sm[];
    float* sW1 = sm;
    float* sW2 = sm + 16384;
    float* sX1 = sm + 32768;            // 64*XPAD
    float* sX2 = sX1 + 64 * XPAD;
    int tid = threadIdx.x;
    int base = blockIdx.x * 64;
    const float4* w14 = (const float4*)W1;
    const float4* w24 = (const float4*)W2;
#pragma unroll
    for (int i = 0; i < 16; i++) {
        ((float4*)sW1)[tid + 256 * i] = w14[tid + 256 * i];
        ((float4*)sW2)[tid + 256 * i] = w24[tid + 256 * i];
    }
    for (int i = tid; i < 64 * HD; i += 256) {
        int r = i >> 7, c = i & 127;
        int gr = base + r;
        float v1 = 0.f, v2 = 0.f;
        if (gr < NN) { v1 = X1[gr * HD + c]; v2 = X2[gr * HD + c]; }
        sX1[r * XPAD + c] = v1;
        sX2[r * XPAD + c] = v2;
    }
    __syncthreads();
    int ti = tid >> 4, tj = tid & 15;
    int r0 = ti * 4, c0 = tj * 8;
    float acc[4][8];
#pragma unroll
    for (int r = 0; r < 4; r++)
#pragma unroll
        for (int c = 0; c < 8; c++) acc[r][c] = bias[c0 + c];
#pragma unroll 8
    for (int k = 0; k < HD; k++) {
        float a1[4], a2[4];
#pragma unroll
        for (int r = 0; r < 4; r++) { a1[r] = sX1[(r0 + r) * XPAD + k]; a2[r] = sX2[(r0 + r) * XPAD + k]; }
        float4 u0 = *(const float4*)&sW1[k * HD + c0];
        float4 u1 = *(const float4*)&sW1[k * HD + c0 + 4];
        float4 v0 = *(const float4*)&sW2[k * HD + c0];
        float4 v1 = *(const float4*)&sW2[k * HD + c0 + 4];
#pragma unroll
        for (int r = 0; r < 4; r++) {
            acc[r][0] += a1[r] * u0.x + a2[r] * v0.x;
            acc[r][1] += a1[r] * u0.y + a2[r] * v0.y;
            acc[r][2] += a1[r] * u0.z + a2[r] * v0.z;
            acc[r][3] += a1[r] * u0.w + a2[r] * v0.w;
            acc[r][4] += a1[r] * u1.x + a2[r] * v1.x;
            acc[r][5] += a1[r] * u1.y + a2[r] * v1.y;
            acc[r][6] += a1[r] * u1.z + a2[r] * v1.z;
            acc[r][7] += a1[r] * u1.w + a2[r] * v1.w;
        }
    }
#pragma unroll
    for (int r = 0; r < 4; r++) {
        int gr = base + r0 + r;
        if (gr < NN) {
#pragma unroll
            for (int c = 0; c < 8; c++) Y[gr * HD + c0 + c] = siluf(acc[r][c]);
        }
    }
}

// ---------------- persistent split-bf16 tensor-core edge kernel ----------------
// Per 128-edge tile (8 warps: warp=(mg,ch), mg 0..3 -> 32 edges, ch 0..1 -> 64 cols):
//   t = silu(hA[row] + hB[col] + d2*wd + ea@W1e)      fp32 -> (t_hi, t_lo) bf16 pair
//   m = silu(t @ e_w2 + e_b2)  via 3x bf16 mma        -> red.v2 agg[row] += m; m -> hi/lo smem
//   w = sum_c silu(m @ c_w1 + c_b1)[c] * c_w2[c]      -> posacc[row] += rel*w
// Weights staged in smem ONCE per block per layer, split hi/lo, transposed [n][k/2].
__global__ void __launch_bounds__(256, 1)
k_edge_tc(const int* __restrict__ ei, const float* __restrict__ ea,
          const float* __restrict__ w1tail,
          const float* __restrict__ eW2, const float* __restrict__ eB2,
          const float* __restrict__ cW1, const float* __restrict__ cB1,
          const float* __restrict__ cW2) {
    extern __shared__ uint32_t smu[];
    uint32_t* sW2h = smu;                 // 128*WS
    uint32_t* sW2l = smu + 128 * WS;
    uint32_t* sC1h = smu + 2 * 128 * WS;
    uint32_t* sC1l = smu + 3 * 128 * WS;
    uint32_t* sAh  = smu + 4 * 128 * WS;  // t then m, hi halves
    uint32_t* sAl  = smu + 5 * 128 * WS;  // lo halves
    float* ext = (float*)(smu + 6 * 128 * WS);
    float* sWd  = ext;            // 128
    float* sW1e = ext + 128;      // 512
    float* sB2  = ext + 640;      // 128
    float* sCb  = ext + 768;      // 128
    float* sC2  = ext + 896;      // 128
    float* sD2  = ext + 1024;     // 128
    float* sRel = ext + 1152;     // 384
    float* sEA  = ext + 1536;     // 512
    float* sWs  = ext + 2048;     // 256
    int* sRow   = (int*)(ext + 2304); // 128
    int* sCol   = (int*)(ext + 2432); // 128

    int tid = threadIdx.x;

    // --- stage weights once: split hi/lo bf16, transposed [n][k/2] packed ---
    for (int i = tid; i < 128 * 64; i += 256) {
        int n = i >> 6, kp = i & 63;
        float w0 = eW2[(2 * kp) * HD + n];
        float w1 = eW2[(2 * kp + 1) * HD + n];
        float h0, l0, h1, l1;
        bsplit(w0, h0, l0); bsplit(w1, h1, l1);
        sW2h[n * WS + kp] = pack2bf(h0, h1);
        sW2l[n * WS + kp] = pack2bf(l0, l1);
        w0 = cW1[(2 * kp) * HD + n];
        w1 = cW1[(2 * kp + 1) * HD + n];
        bsplit(w0, h0, l0); bsplit(w1, h1, l1);
        sC1h[n * WS + kp] = pack2bf(h0, h1);
        sC1l[n * WS + kp] = pack2bf(l0, l1);
    }
    for (int i = tid; i < 5 * 128; i += 256) {
        float v = w1tail[i];
        if (i < 128) sWd[i] = v; else sW1e[i - 128] = v;
    }
    if (tid < 128) { sB2[tid] = eB2[tid]; sCb[tid] = cB1[tid]; sC2[tid] = cW2[tid]; }

    int warp = tid >> 5, lane = tid & 31;
    int mg = warp >> 1, ch = warp & 1;
    int gid = lane >> 2, tg = lane & 3;

    const float4* hA4 = (const float4*)g_hA;
    const float4* hB4 = (const float4*)g_hB;

    for (int tile = blockIdx.x; tile < NT; tile += gridDim.x) {
        int base = tile * ET;
        int ne = EE - base; if (ne > ET) ne = ET;

        __syncthreads();  // previous tile fully consumed / staging visible

        if (tid < ET) {
            bool v = tid < ne;
            int e = base + tid;
            int r = 0, c = 0;
            float rx = 0.f, ry = 0.f, rz = 0.f;
            if (v) {
                r = ei[e]; c = ei[EE + e];
                rx = g_pos[r * 3 + 0] - g_pos[c * 3 + 0];
                ry = g_pos[r * 3 + 1] - g_pos[c * 3 + 1];
                rz = g_pos[r * 3 + 2] - g_pos[c * 3 + 2];
#pragma unroll
                for (int k = 0; k < 4; k++) sEA[tid * 4 + k] = ea[e * 4 + k];
            } else {
#pragma unroll
                for (int k = 0; k < 4; k++) sEA[tid * 4 + k] = 0.f;
            }
            sRow[tid] = r; sCol[tid] = c;
            sRel[tid * 3 + 0] = rx; sRel[tid * 3 + 1] = ry; sRel[tid * 3 + 2] = rz;
            sD2[tid] = rx * rx + ry * ry + rz * rz;
        }
        __syncthreads();

        // --- t-phase: gather + edge-feature fold + silu + hi/lo split ---
#pragma unroll
        for (int it = 0; it < 16; it++) {
            int i = tid + it * 256;
            int e = i >> 5, jg = i & 31;
            float vx = 0.f, vy = 0.f, vz = 0.f, vw = 0.f;
            if (e < ne) {
                float4 a = hA4[sRow[e] * 32 + jg];
                float4 b = hB4[sCol[e] * 32 + jg];
                float d2 = sD2[e];
                float4 wd = ((const float4*)sWd)[jg];
                vx = a.x + b.x + d2 * wd.x;
                vy = a.y + b.y + d2 * wd.y;
                vz = a.z + b.z + d2 * wd.z;
                vw = a.w + b.w + d2 * wd.w;
#pragma unroll
                for (int k = 0; k < 4; k++) {
                    float ek = sEA[e * 4 + k];
                    float4 we = ((const float4*)sW1e)[k * 32 + jg];
                    vx += ek * we.x; vy += ek * we.y; vz += ek * we.z; vw += ek * we.w;
                }
                vx = siluf(vx); vy = siluf(vy); vz = siluf(vz); vw = siluf(vw);
            }
            float hx, lx, hy, ly, hz, lz, hw, lw;
            bsplit(vx, hx, lx); bsplit(vy, hy, ly);
            bsplit(vz, hz, lz); bsplit(vw, hw, lw);
            int off = e * WS + 2 * jg;
            sAh[off] = pack2bf(hx, hy); sAh[off + 1] = pack2bf(hz, hw);
            sAl[off] = pack2bf(lx, ly); sAl[off + 1] = pack2bf(lz, lw);
        }
        __syncthreads();

        // --- GEMM1: m = silu(t @ e_w2 + e_b2), 3-term split bf16 ---
        float acc[2][8][4];
#pragma unroll
        for (int mt = 0; mt < 2; mt++)
#pragma unroll
            for (int j = 0; j < 8; j++) {
                int col = ch * 64 + j * 8 + 2 * tg;
                acc[mt][j][0] = sB2[col]; acc[mt][j][1] = sB2[col + 1];
                acc[mt][j][2] = sB2[col]; acc[mt][j][3] = sB2[col + 1];
            }
#pragma unroll
        for (int kc = 0; kc < 8; kc++) {
            int kp0 = kc * 8;
            uint32_t ah[2][4], al[2][4];
#pragma unroll
            for (int mt = 0; mt < 2; mt++) {
                int R = mg * 32 + mt * 16;
                ah[mt][0] = sAh[(R + gid) * WS + kp0 + tg];
                ah[mt][1] = sAh[(R + 8 + gid) * WS + kp0 + tg];
                ah[mt][2] = sAh[(R + gid) * WS + kp0 + 4 + tg];
                ah[mt][3] = sAh[(R + 8 + gid) * WS + kp0 + 4 + tg];
                al[mt][0] = sAl[(R + gid) * WS + kp0 + tg];
                al[mt][1] = sAl[(R + 8 + gid) * WS + kp0 + tg];
                al[mt][2] = sAl[(R + gid) * WS + kp0 + 4 + tg];
                al[mt][3] = sAl[(R + 8 + gid) * WS + kp0 + 4 + tg];
            }
#pragma unroll
            for (int j = 0; j < 8; j++) {
                int n = ch * 64 + j * 8 + gid;
                uint32_t bh0 = sW2h[n * WS + kp0 + tg];
                uint32_t bh1 = sW2h[n * WS + kp0 + 4 + tg];
                uint32_t bl0 = sW2l[n * WS + kp0 + tg];
                uint32_t bl1 = sW2l[n * WS + kp0 + 4 + tg];
                mma_bf16(acc[0][j], ah[0], bh0, bh1);
                mma_bf16(acc[1][j], ah[1], bh0, bh1);
                mma_bf16(acc[0][j], al[0], bh0, bh1);
                mma_bf16(acc[1][j], al[1], bh0, bh1);
                mma_bf16(acc[0][j], ah[0], bl0, bl1);
                mma_bf16(acc[1][j], ah[1], bl0, bl1);
            }
        }
        __syncthreads();

        // --- silu, store m (hi/lo) over t, scatter agg via vector red ---
#pragma unroll
        for (int mt = 0; mt < 2; mt++) {
            int r1 = mg * 32 + mt * 16 + gid;
            int r2 = r1 + 8;
#pragma unroll
            for (int j = 0; j < 8; j++) {
                int col = ch * 64 + j * 8 + 2 * tg;
                int cw = ch * 32 + j * 4 + tg;
                float m00 = siluf(acc[mt][j][0]), m01 = siluf(acc[mt][j][1]);
                float m10 = siluf(acc[mt][j][2]), m11 = siluf(acc[mt][j][3]);
                float h0, l0, h1, l1;
                bsplit(m00, h0, l0); bsplit(m01, h1, l1);
                sAh[r1 * WS + cw] = pack2bf(h0, h1);
                sAl[r1 * WS + cw] = pack2bf(l0, l1);
                bsplit(m10, h0, l0); bsplit(m11, h1, l1);
                sAh[r2 * WS + cw] = pack2bf(h0, h1);
                sAl[r2 * WS + cw] = pack2bf(l0, l1);
                if (r1 < ne) red2(&g_agg[sRow[r1] * HD + col], m00, m01);
                if (r2 < ne) red2(&g_agg[sRow[r2] * HD + col], m10, m11);
            }
        }
        __syncthreads();

        // --- GEMM2: cm = silu(m @ c_w1 + c_b1); w = cm . c_w2 ---
        float acc2[2][8][4];
#pragma unroll
        for (int mt = 0; mt < 2; mt++)
#pragma unroll
            for (int j = 0; j < 8; j++) {
                int col = ch * 64 + j * 8 + 2 * tg;
                acc2[mt][j][0] = sCb[col]; acc2[mt][j][1] = sCb[col + 1];
                acc2[mt][j][2] = sCb[col]; acc2[mt][j][3] = sCb[col + 1];
            }
#pragma unroll
        for (int kc = 0; kc < 8; kc++) {
            int kp0 = kc * 8;
            uint32_t ah[2][4], al[2][4];
#pragma unroll
            for (int mt = 0; mt < 2; mt++) {
                int R = mg * 32 + mt * 16;
                ah[mt][0] = sAh[(R + gid) * WS + kp0 + tg];
                ah[mt][1] = sAh[(R + 8 + gid) * WS + kp0 + tg];
                ah[mt][2] = sAh[(R + gid) * WS + kp0 + 4 + tg];
                ah[mt][3] = sAh[(R + 8 + gid) * WS + kp0 + 4 + tg];
                al[mt][0] = sAl[(R + gid) * WS + kp0 + tg];
                al[mt][1] = sAl[(R + 8 + gid) * WS + kp0 + tg];
                al[mt][2] = sAl[(R + gid) * WS + kp0 + 4 + tg];
                al[mt][3] = sAl[(R + 8 + gid) * WS + kp0 + 4 + tg];
            }
#pragma unroll
            for (int j = 0; j < 8; j++) {
                int n = ch * 64 + j * 8 + gid;
                uint32_t bh0 = sC1h[n * WS + kp0 + tg];
                uint32_t bh1 = sC1h[n * WS + kp0 + 4 + tg];
                uint32_t bl0 = sC1l[n * WS + kp0 + tg];
                uint32_t bl1 = sC1l[n * WS + kp0 + 4 + tg];
                mma_bf16(acc2[0][j], ah[0], bh0, bh1);
                mma_bf16(acc2[1][j], ah[1], bh0, bh1);
                mma_bf16(acc2[0][j], al[0], bh0, bh1);
                mma_bf16(acc2[1][j], al[1], bh0, bh1);
                mma_bf16(acc2[0][j], ah[0], bl0, bl1);
                mma_bf16(acc2[1][j], ah[1], bl0, bl1);
            }
        }

#pragma unroll
        for (int mt = 0; mt < 2; mt++) {
            float s1 = 0.f, s2 = 0.f;
#pragma unroll
            for (int j = 0; j < 8; j++) {
                int col = ch * 64 + j * 8 + 2 * tg;
                s1 += siluf(acc2[mt][j][0]) * sC2[col] + siluf(acc2[mt][j][1]) * sC2[col + 1];
                s2 += siluf(acc2[mt][j][2]) * sC2[col] + siluf(acc2[mt][j][3]) * sC2[col + 1];
            }
            s1 += __shfl_xor_sync(0xffffffffu, s1, 1);
            s1 += __shfl_xor_sync(0xffffffffu, s1, 2);
            s2 += __shfl_xor_sync(0xffffffffu, s2, 1);
            s2 += __shfl_xor_sync(0xffffffffu, s2, 2);
            if (tg == 0) {
                int r1 = mg * 32 + mt * 16 + gid;
                sWs[ch * 128 + r1] = s1;
                sWs[ch * 128 + r1 + 8] = s2;
            }
        }
        __syncthreads();

        if (tid < ne) {
            float w = sWs[tid] + sWs[128 + tid];
            int rb = sRow[tid] * 3;
            atomicAdd(&g_posacc[rb + 0], sRel[tid * 3 + 0] * w);
            atomicAdd(&g_posacc[rb + 1], sRel[tid * 3 + 1] * w);
            atomicAdd(&g_posacc[rb + 2], sRel[tid * 3 + 2] * w);
        }
    }
}

// ---------------- pos update + per-layer scratch reset ----------------
__global__ void k_posupd() {
    int stride = gridDim.x * blockDim.x;
    for (int i = blockIdx.x * blockDim.x + threadIdx.x; i < NN * HD; i += stride) {
        g_agg[i] = 0.f;
        if (i < NN * 3) {
            g_pos[i] += g_posacc[i] / fmaxf(g_deg[i / 3], 1.f);
            g_posacc[i] = 0.f;
        }
    }
}

// ---------------- pooling + MLP head ----------------
__global__ void k_head(const float* __restrict__ h1w, const float* __restrict__ h1b,
                       const float* __restrict__ h2w, const float* __restrict__ h2b,
                       const float* __restrict__ h3w, const float* __restrict__ h3b,
                       float* __restrict__ out) {
    __shared__ float sg[2 * HD];
    __shared__ float sz1[128];
    __shared__ float sz2[64];
    int g = blockIdx.x;
    int f = threadIdx.x;  // 128 threads
    float acc = 0.f;
    int nb = g * NPG;
    for (int n = 0; n < NPG; n++) acc += g_h[(nb + n) * HD + f];
    sg[f] = acc;
    sg[HD + f] = acc * (1.f / NPG);
    __syncthreads();
    float z = h1b[f];
    for (int k = 0; k < 2 * HD; k++) z += sg[k] * h1w[k * 128 + f];
    sz1[f] = fmaxf(z, 0.f);
    __syncthreads();
    if (f < 64) {
        float z2 = h2b[f];
        for (int k = 0; k < 128; k++) z2 += sz1[k] * h2w[k * 64 + f];
        sz2[f] = fmaxf(z2, 0.f);
    }
    __syncthreads();
    if (f == 0) {
        float o = h3b[0];
        for (int k = 0; k < 64; k++) o += sz2[k] * h3w[k];
        out[g] = o;
    }
}

// ---------------- host orchestration ----------------
extern "C" void kernel_launch(void* const* d_in, const int* in_sizes, int n_in,
                              void* d_out, int out_size) {
    (void)in_sizes; (void)n_in; (void)out_size;
    const float* x    = (const float*)d_in[0];
    const float* pos  = (const float*)d_in[1];
    const int*   ei   = (const int*)d_in[2];
    const float* ea   = (const float*)d_in[3];
    const float* Wp   = (const float*)d_in[6];
    const float* bp   = (const float*)d_in[7];
    const float* Wl   = (const float*)d_in[8];
    const float* bl   = (const float*)d_in[9];
    const float* bng  = (const float*)d_in[10];
    const float* bnb  = (const float*)d_in[11];
    const float* e_w1 = (const float*)d_in[12];
    const float* e_b1 = (const float*)d_in[13];
    const float* e_w2 = (const float*)d_in[14];
    const float* e_b2 = (const float*)d_in[15];
    const float* c_w1 = (const float*)d_in[16];
    const float* c_b1 = (const float*)d_in[17];
    const float* c_w2 = (const float*)d_in[18];
    const float* n_w1 = (const float*)d_in[19];
    const float* n_b1 = (const float*)d_in[20];
    const float* n_w2 = (const float*)d_in[21];
    const float* n_b2 = (const float*)d_in[22];
    const float* h1w  = (const float*)d_in[23];
    const float* h1b  = (const float*)d_in[24];
    const float* h2w  = (const float*)d_in[25];
    const float* h2b  = (const float*)d_in[26];
    const float* h3w  = (const float*)d_in[27];
    const float* h3b  = (const float*)d_in[28];
    float* out = (float*)d_out;

    float *p_h, *p_hA, *p_hB, *p_agg, *p_u1;
    cudaGetSymbolAddress((void**)&p_h,   g_h);
    cudaGetSymbolAddress((void**)&p_hA,  g_hA);
    cudaGetSymbolAddress((void**)&p_hB,  g_hB);
    cudaGetSymbolAddress((void**)&p_agg, g_agg);
    cudaGetSymbolAddress((void**)&p_u1,  g_u1);

    const int smem_gemm = (128 * 128 + 128 * XPAD) * 4;
    const int smem_dual = (2 * 128 * 128 + 2 * 64 * XPAD) * 4;
    const int smem_edge = (6 * 128 * WS + 2560) * 4;  // 219,136 B

    cudaFuncSetAttribute(k_gemm<false, true, false>,  cudaFuncAttributeMaxDynamicSharedMemorySize, smem_gemm);
    cudaFuncSetAttribute(k_gemm<false, false, false>, cudaFuncAttributeMaxDynamicSharedMemorySize, smem_gemm);
    cudaFuncSetAttribute(k_gemm<false, true, true>,   cudaFuncAttributeMaxDynamicSharedMemorySize, smem_gemm);
    cudaFuncSetAttribute(k_dual, cudaFuncAttributeMaxDynamicSharedMemorySize, smem_dual);
    cudaFuncSetAttribute(k_edge_tc, cudaFuncAttributeMaxDynamicSharedMemorySize, smem_edge);

    k_init<<<2048, 256>>>(pos);
    k_proj<<<2048, 128>>>(x, Wp, bp, Wl, bl);
    k_stats<<<512, 128>>>();
    k_bn<<<2048, 256>>>(bng, bnb);
    k_deg<<<(EE + 255) / 256, 256>>>(ei);

    for (int l = 0; l < NL; l++) {
        const float* w1l = e_w1 + (size_t)l * 261 * HD;
        // hA = h @ W1a + e_b1[l];  hB = h @ W1b
        k_gemm<false, true, false><<<391, 256, smem_gemm>>>(p_h, w1l, e_b1 + l * HD, nullptr, p_hA);
        k_gemm<false, false, false><<<391, 256, smem_gemm>>>(p_h, w1l + 128 * HD, nullptr, nullptr, p_hB);
        // persistent fused edge MLP (split-bf16 tensor cores) + scatters
        k_edge_tc<<<152, 256, smem_edge>>>(
            ei, ea, w1l + 256 * HD,
            e_w2 + (size_t)l * HD * HD, e_b2 + l * HD,
            c_w1 + (size_t)l * HD * HD, c_b1 + l * HD, c_w2 + l * HD);
        // u1 = silu(h @ nW1a + agg @ nW1b + n_b1[l])
        k_dual<<<782, 256, smem_dual>>>(p_h, n_w1 + (size_t)l * 2 * HD * HD,
                                        p_agg, n_w1 + (size_t)l * 2 * HD * HD + 128 * HD,
                                        n_b1 + l * HD, p_u1);
        // pos += posacc/deg; zero agg/posacc for next layer
        k_posupd<<<2048, 256>>>();
        // h = h + u1 @ n_w2[l] + n_b2[l]
        k_gemm<false, true, true><<<391, 256, smem_gemm>>>(p_u1, n_w2 + (size_t)l * HD * HD,
                                                           n_b2 + l * HD, p_h, p_h);
    }

    k_head<<<GG, 128>>>(h1w, h1b, h2w, h2b, h3w, h3b, out);
}